// round 11
// baseline (speedup 1.0000x reference)
#include <cuda_runtime.h>
#include <cuda_fp16.h>
#include <math.h>
#include <stdint.h>

// Problem constants (fixed by the dataset)
#define NMAX   100000
#define DIMC   128
#define HID    512
#define KTAPS  343

// ---------------- scratch (device globals; no allocation allowed) ----------
__device__ __half g_x1[(size_t)NMAX * DIMC];    // post dwconv+LN (fp16, 25.6 MB)
__device__ __half g_w1t[HID * DIMC];            // w1^T [n][k]
__device__ __half g_h[(size_t)NMAX * HID];      // gelu(h) fp16 (102.4 MB)
__device__ float  g_ssq[HID];
__device__ float  g_s  [HID];                   // GRN scale: grn_g*nx + 1
__device__ __half g_w2t[DIMC * HID];            // (diag(s) w2)^T [n][k]
__device__ float  g_b2p[DIMC];                  // grn_b @ w2 + b2

// ======================= helpers ===========================================
__device__ __forceinline__ uint32_t smem_u32(const void* p) {
    uint32_t a;
    asm("{ .reg .u64 t; cvta.to.shared.u64 t, %1; cvt.u32.u64 %0, t; }" : "=r"(a) : "l"(p));
    return a;
}
__device__ __forceinline__ float gelu_exact(float v) {
    return 0.5f * v * (1.0f + erff(v * 0.70710678118654752f));
}
// swizzled byte offset within a [rows][64 fp16] (128B/row) smem tile
__device__ __forceinline__ uint32_t sw_off(int row, int u) {   // u = 16B unit 0..7
    return (uint32_t)((row * 128 + u * 16) ^ ((row & 7) << 4));
}
__device__ __forceinline__ void ldsm4(uint32_t* r, uint32_t addr) {
    asm volatile("ldmatrix.sync.aligned.m8n8.x4.shared.b16 {%0,%1,%2,%3}, [%4];"
        : "=r"(r[0]), "=r"(r[1]), "=r"(r[2]), "=r"(r[3]) : "r"(addr));
}
__device__ __forceinline__ void mma16816(float* c, const uint32_t* a, const uint32_t* b) {
    asm volatile("mma.sync.aligned.m16n8k16.row.col.f32.f16.f16.f32 "
        "{%0,%1,%2,%3}, {%4,%5,%6,%7}, {%8,%9}, {%0,%1,%2,%3};"
        : "+f"(c[0]), "+f"(c[1]), "+f"(c[2]), "+f"(c[3])
        : "r"(a[0]), "r"(a[1]), "r"(a[2]), "r"(a[3]), "r"(b[0]), "r"(b[1]));
}
__device__ __forceinline__ void cp16(uint32_t dst, const void* src, bool pred) {
    int sz = pred ? 16 : 0;
    asm volatile("cp.async.cg.shared.global [%0], [%1], 16, %2;"
        :: "r"(dst), "l"(src), "r"(sz));
}
#define CP_COMMIT() asm volatile("cp.async.commit_group;" ::: "memory")
#define CP_WAIT(N)  asm volatile("cp.async.wait_group %0;" :: "n"(N) : "memory")

// ---------------- Kernel A: sparse depthwise conv + LayerNorm -> fp16 ------
// (exact 350.3us-verified form: per-chunk loads keep regs low -> max warps)
__global__ __launch_bounds__(256) void dwconv_ln_k(
    const float* __restrict__ feats, const int* __restrict__ nbr,
    const float* __restrict__ dw_w, const float* __restrict__ dw_b,
    const float* __restrict__ ln_g, const float* __restrict__ ln_b, int n)
{
    int site = (blockIdx.x * blockDim.x + threadIdx.x) >> 5;
    int lane = threadIdx.x & 31;
    if (site >= n) return;

    const int* row = nbr + (size_t)site * KTAPS;
    float4 acc = make_float4(0.f, 0.f, 0.f, 0.f);

    for (int k0 = 0; k0 < KTAPS; k0 += 32) {
        int k   = k0 + lane;
        int idx = (k < KTAPS) ? row[k] : n;
        unsigned valid = __ballot_sync(0xffffffffu, idx < n);
        while (valid) {
            int b = __ffs(valid) - 1;
            valid &= valid - 1;
            int j  = __shfl_sync(0xffffffffu, idx, b);
            int kk = k0 + b;
            float4 f = *(const float4*)(feats + (size_t)j * DIMC + lane * 4);
            float4 w = *(const float4*)(dw_w + kk * DIMC + lane * 4);
            acc.x = fmaf(f.x, w.x, acc.x);
            acc.y = fmaf(f.y, w.y, acc.y);
            acc.z = fmaf(f.z, w.z, acc.z);
            acc.w = fmaf(f.w, w.w, acc.w);
        }
    }
    float4 bb = *(const float4*)(dw_b + lane * 4);
    acc.x += bb.x; acc.y += bb.y; acc.z += bb.z; acc.w += bb.w;

    float s1 = acc.x + acc.y + acc.z + acc.w;
    float s2 = acc.x*acc.x + acc.y*acc.y + acc.z*acc.z + acc.w*acc.w;
    #pragma unroll
    for (int o = 16; o; o >>= 1) {
        s1 += __shfl_xor_sync(0xffffffffu, s1, o);
        s2 += __shfl_xor_sync(0xffffffffu, s2, o);
    }
    float mean = s1 * (1.f / DIMC);
    float var  = s2 * (1.f / DIMC) - mean * mean;
    float rstd = rsqrtf(var + 1e-6f);

    float4 g = *(const float4*)(ln_g + lane * 4);
    float4 b = *(const float4*)(ln_b + lane * 4);
    float v0 = (acc.x - mean) * rstd * g.x + b.x;
    float v1 = (acc.y - mean) * rstd * g.y + b.y;
    float v2 = (acc.z - mean) * rstd * g.z + b.z;
    float v3 = (acc.w - mean) * rstd * g.w + b.w;

    size_t o = (size_t)site * DIMC + lane * 4;
    *(half2*)(g_x1 + o)     = __floats2half2_rn(v0, v1);
    *(half2*)(g_x1 + o + 2) = __floats2half2_rn(v2, v3);
}

// ---------------- prep: w1t[n][k] = fp16(w1[k][n]); also zero ssq ----------
__global__ void w1t_prep_k(const float* __restrict__ w1)
{
    int idx = blockIdx.x * blockDim.x + threadIdx.x;   // 65536 = 512*128
    if (idx < HID) g_ssq[idx] = 0.f;
    if (idx < HID * DIMC) {
        int nrow = idx >> 7, k = idx & 127;
        g_w1t[idx] = __float2half_rn(w1[(size_t)k * HID + nrow]);
    }
}

// ============== async chunk loader =========================================
__device__ __forceinline__ void load_chunk_async(
    uint32_t sA, uint32_t sB,
    const __half* __restrict__ A, int a_stride,
    const __half* __restrict__ B, int b_stride,
    int m0, int n_valid, int nb0, int kc, int tid)
{
    #pragma unroll
    for (int i = 0; i < 2; i++) {
        int idx = tid + i * 512;
        int row = idx >> 3, u = idx & 7;
        bool ok = (m0 + row < n_valid);
        size_t go = (size_t)(m0 + row) * a_stride + kc * 64 + u * 8;
        cp16(sA + sw_off(row, u), A + go, ok);
    }
    #pragma unroll
    for (int i = 0; i < 2; i++) {
        int idx = tid + i * 512;
        int row = idx >> 3, u = idx & 7;
        size_t go = (size_t)(nb0 + row) * b_stride + kc * 64 + u * 8;
        cp16(sB + sw_off(row, u), B + go, true);
    }
    CP_COMMIT();
}

// ---------------- Kernel B: GEMM1  h = gelu(x1 @ w1 + b1), + ssq -----------
// Block 128M x 128N, K=128 (2 chunks of 64), 512 thr = 16 warps (4m x 4n),
// warp tile 32x32. smem: 2 stages x (A 16KB + B 16KB) = 64KB. 2 CTAs/SM.
// grid = (4 N-tiles, mtiles): adjacent CTAs share the same A tile via L2.
__global__ __launch_bounds__(512, 2) void gemm1_tc(const float* __restrict__ b1, int n)
{
    extern __shared__ char smem[];
    const int STG = 32768;
    __shared__ float scs[128];

    int tid = threadIdx.x;
    int wid = tid >> 5, lane = tid & 31;
    int wm = wid >> 2, wn = wid & 3;
    int lr = lane & 15, lh = lane >> 4;
    int m0 = blockIdx.y * 128;
    int n0 = blockIdx.x * 128;

    if (tid < 128) scs[tid] = 0.f;

    uint32_t base = smem_u32(smem);
    uint32_t arow0 = (uint32_t)((wm * 32 + lr) * 128);
    uint32_t brow0 = (uint32_t)((wn * 32 + lr) * 128);
    uint32_t sx    = (uint32_t)((lr & 7) << 4);

    float acc[2][4][4];
    #pragma unroll
    for (int mf = 0; mf < 2; mf++)
        #pragma unroll
        for (int nf = 0; nf < 4; nf++)
            #pragma unroll
            for (int r = 0; r < 4; r++) acc[mf][nf][r] = 0.f;

    #pragma unroll
    for (int kc = 0; kc < 2; kc++) {
        uint32_t sb = base + kc * STG;
        load_chunk_async(sb, sb + 16384,
                         g_x1, DIMC, g_w1t, DIMC,
                         m0, n, n0, kc, tid);
    }

    #pragma unroll
    for (int kc = 0; kc < 2; kc++) {
        if (kc == 0) { CP_WAIT(1); } else { CP_WAIT(0); }
        __syncthreads();
        uint32_t uA = base + kc * STG, uB = uA + 16384;
        #pragma unroll
        for (int ks = 0; ks < 4; ks++) {
            uint32_t xu = (uint32_t)(((ks * 2 + lh) << 4)) ^ sx;
            uint32_t ah[2][4];
            #pragma unroll
            for (int mf = 0; mf < 2; mf++)
                ldsm4(ah[mf], uA + arow0 + mf * 2048 + xu);
            #pragma unroll
            for (int nh = 0; nh < 2; nh++) {
                uint32_t t[4], bf[2][2];
                ldsm4(t, uB + brow0 + nh * 2048 + xu);
                bf[0][0] = t[0]; bf[0][1] = t[2];
                bf[1][0] = t[1]; bf[1][1] = t[3];
                #pragma unroll
                for (int mf = 0; mf < 2; mf++)
                    #pragma unroll
                    for (int j = 0; j < 2; j++)
                        mma16816(acc[mf][nh * 2 + j], ah[mf], bf[j]);
            }
        }
        __syncthreads();
    }

    // epilogue: bias + GELU, fp16 store, per-column ssq (fp32, unrounded)
    int g = lane >> 2, q = lane & 3;
    float csq[8];
    #pragma unroll
    for (int i = 0; i < 8; i++) csq[i] = 0.f;
    #pragma unroll
    for (int mf = 0; mf < 2; mf++) {
        #pragma unroll
        for (int nf = 0; nf < 4; nf++) {
            int col = n0 + wn * 32 + nf * 8 + q * 2;
            float bia0 = b1[col], bia1 = b1[col + 1];
            #pragma unroll
            for (int half_i = 0; half_i < 2; half_i++) {
                int m = m0 + wm * 32 + mf * 16 + g + half_i * 8;
                if (m < n) {
                    float v0 = gelu_exact(acc[mf][nf][half_i*2+0] + bia0);
                    float v1 = gelu_exact(acc[mf][nf][half_i*2+1] + bia1);
                    *(half2*)(g_h + (size_t)m * HID + col) = __floats2half2_rn(v0, v1);
                    csq[nf*2+0] += v0 * v0;
                    csq[nf*2+1] += v1 * v1;
                }
            }
        }
    }
    __syncthreads();
    #pragma unroll
    for (int nf = 0; nf < 4; nf++) {
        atomicAdd(&scs[wn * 32 + nf * 8 + q * 2],     csq[nf*2+0]);
        atomicAdd(&scs[wn * 32 + nf * 8 + q * 2 + 1], csq[nf*2+1]);
    }
    __syncthreads();
    if (tid < 128) atomicAdd(&g_ssq[n0 + tid], scs[tid]);
}

// ---------------- Kernel D1: GRN channel scale -----------------------------
__global__ void grn_scale_k(const float* __restrict__ grn_g)
{
    int c = threadIdx.x;            // 512 threads, 1 block
    float gx = sqrtf(g_ssq[c]);
    __shared__ float red[16];
    __shared__ float mean_s;
    float v = gx;
    #pragma unroll
    for (int o = 16; o; o >>= 1) v += __shfl_xor_sync(0xffffffffu, v, o);
    if ((c & 31) == 0) red[c >> 5] = v;
    __syncthreads();
    if (c < 16) {
        float w = red[c];
        #pragma unroll
        for (int o = 8; o; o >>= 1) w += __shfl_xor_sync(0xffffu, w, o);
        if (c == 0) mean_s = w * (1.f / HID);
    }
    __syncthreads();
    float nx = gx / (mean_s + 1e-6f);
    g_s[c] = grn_g[c] * nx + 1.0f;
}

// ---------------- Kernel D2: w2t[n][k] = fp16(s[k]*w2[k][n]) ---------------
__global__ void build_w2t_k(const float* __restrict__ w2)
{
    int idx = blockIdx.x * blockDim.x + threadIdx.x;   // 65536 = 128*512
    if (idx < DIMC * HID) {
        int nrow = idx >> 9, k = idx & 511;
        g_w2t[idx] = __float2half_rn(g_s[k] * w2[(size_t)k * DIMC + nrow]);
    }
}

// ---------------- Kernel D3: b2' = grn_b @ w2 + b2 (no g_s dependency) -----
__global__ void build_b2p_k(const float* __restrict__ grn_b,
                            const float* __restrict__ w2,
                            const float* __restrict__ b2)
{
    int c = threadIdx.x;            // 128 threads
    float acc = 0.f;
    for (int k = 0; k < HID; k++) acc = fmaf(grn_b[k], w2[(size_t)k * DIMC + c], acc);
    g_b2p[c] = b2[c] + acc;
}

// ---------------- Kernel E: GEMM2  out = h @ w2' + b2' + feats -------------
// Block 128M x 128N, K=512 (8 chunks, 2-stage ring), 512 thr, warp 32x32.
// smem: 2 stages x (A 16KB + B 16KB) = 64KB. 2 CTAs/SM.
__global__ __launch_bounds__(512, 2) void gemm2_tc(
    const float* __restrict__ feats, float* __restrict__ out, int n)
{
    extern __shared__ char smem[];
    const int STG = 32768;

    int tid = threadIdx.x;
    int wid = tid >> 5, lane = tid & 31;
    int wm = wid >> 2, wn = wid & 3;
    int lr = lane & 15, lh = lane >> 4;
    int m0 = blockIdx.x * 128;

    uint32_t base = smem_u32(smem);
    uint32_t arow0 = (uint32_t)((wm * 32 + lr) * 128);
    uint32_t brow0 = (uint32_t)((wn * 32 + lr) * 128);
    uint32_t sx    = (uint32_t)((lr & 7) << 4);

    float acc[2][4][4];
    #pragma unroll
    for (int mf = 0; mf < 2; mf++)
        #pragma unroll
        for (int nf = 0; nf < 4; nf++)
            #pragma unroll
            for (int r = 0; r < 4; r++) acc[mf][nf][r] = 0.f;

    load_chunk_async(base, base + 16384,
                     g_h, HID, g_w2t, HID,
                     m0, n, 0, 0, tid);

    for (int kc = 0; kc < 8; kc++) {
        if (kc < 7) {
            uint32_t sb = base + ((kc + 1) & 1) * STG;
            load_chunk_async(sb, sb + 16384,
                             g_h, HID, g_w2t, HID,
                             m0, n, 0, kc + 1, tid);
            CP_WAIT(1);
        } else {
            CP_WAIT(0);
        }
        __syncthreads();

        uint32_t uA = base + (kc & 1) * STG, uB = uA + 16384;
        #pragma unroll
        for (int ks = 0; ks < 4; ks++) {
            uint32_t xu = (uint32_t)(((ks * 2 + lh) << 4)) ^ sx;
            uint32_t ah[2][4];
            #pragma unroll
            for (int mf = 0; mf < 2; mf++)
                ldsm4(ah[mf], uA + arow0 + mf * 2048 + xu);
            #pragma unroll
            for (int nh = 0; nh < 2; nh++) {
                uint32_t t[4], bf[2][2];
                ldsm4(t, uB + brow0 + nh * 2048 + xu);
                bf[0][0] = t[0]; bf[0][1] = t[2];
                bf[1][0] = t[1]; bf[1][1] = t[3];
                #pragma unroll
                for (int mf = 0; mf < 2; mf++)
                    #pragma unroll
                    for (int j = 0; j < 2; j++)
                        mma16816(acc[mf][nh * 2 + j], ah[mf], bf[j]);
            }
        }
        __syncthreads();
    }

    // epilogue: + b2' + feats residual, fp32 out
    int g = lane >> 2, q = lane & 3;
    #pragma unroll
    for (int mf = 0; mf < 2; mf++) {
        #pragma unroll
        for (int nf = 0; nf < 4; nf++) {
            int col = wn * 32 + nf * 8 + q * 2;
            float b0 = g_b2p[col], b1v = g_b2p[col + 1];
            #pragma unroll
            for (int half_i = 0; half_i < 2; half_i++) {
                int m = m0 + wm * 32 + mf * 16 + g + half_i * 8;
                if (m < n) {
                    size_t o = (size_t)m * DIMC + col;
                    float2 fr = *(const float2*)(feats + o);
                    float2 ov;
                    ov.x = acc[mf][nf][half_i*2+0] + b0  + fr.x;
                    ov.y = acc[mf][nf][half_i*2+1] + b1v + fr.y;
                    *(float2*)(out + o) = ov;
                }
            }
        }
    }
}

// ---------------------------------------------------------------------------
extern "C" void kernel_launch(void* const* d_in, const int* in_sizes, int n_in,
                              void* d_out, int out_size)
{
    const float* feats = (const float*)d_in[0];
    const int*   nbr   = (const int*)  d_in[1];
    const float* dw_w  = (const float*)d_in[2];
    const float* dw_b  = (const float*)d_in[3];
    const float* ln_g  = (const float*)d_in[4];
    const float* ln_b  = (const float*)d_in[5];
    const float* w1    = (const float*)d_in[6];
    const float* b1    = (const float*)d_in[7];
    const float* grn_g = (const float*)d_in[8];
    const float* grn_b = (const float*)d_in[9];
    const float* w2    = (const float*)d_in[10];
    const float* b2    = (const float*)d_in[11];
    float* out = (float*)d_out;

    int n = in_sizes[0] / DIMC;

    const int SMEM = 64 * 1024;
    cudaFuncSetAttribute(gemm1_tc, cudaFuncAttributeMaxDynamicSharedMemorySize, SMEM);
    cudaFuncSetAttribute(gemm2_tc, cudaFuncAttributeMaxDynamicSharedMemorySize, SMEM);

    int blocks_a = (n * 32 + 255) / 256;
    dwconv_ln_k<<<blocks_a, 256>>>(feats, nbr, dw_w, dw_b, ln_g, ln_b, n);

    w1t_prep_k<<<(HID * DIMC + 255) / 256, 256>>>(w1);
    build_b2p_k<<<1, DIMC>>>(grn_b, w2, b2);   // no g_s dependency — hoisted

    int mtiles = (n + 127) / 128;
    dim3 g1(4, mtiles);                        // N-tiles inner: A-tile L2 reuse
    gemm1_tc<<<g1, 512, SMEM>>>(b1, n);

    grn_scale_k<<<1, HID>>>(grn_g);
    build_w2t_k<<<(DIMC * HID + 255) / 256, 256>>>(w2);

    gemm2_tc<<<mtiles, 512, SMEM>>>(feats, out, n);
}

// round 12
// speedup vs baseline: 1.6337x; 1.6337x over previous
#include <cuda_runtime.h>
#include <cuda_fp16.h>
#include <math.h>
#include <stdint.h>

// Problem constants (fixed by the dataset)
#define NMAX   100000
#define DIMC   128
#define HID    512
#define KTAPS  343

// ---------------- scratch (device globals; no allocation allowed) ----------
__device__ __half g_x1[(size_t)NMAX * DIMC];    // post dwconv+LN (fp16, 25.6 MB)
__device__ __half g_w1t[HID * DIMC];            // w1^T [n][k]
__device__ __half g_h[(size_t)NMAX * HID];      // gelu(h) fp16 (102.4 MB)
__device__ float  g_ssq[HID];
__device__ float  g_s  [HID];                   // GRN scale: grn_g*nx + 1
__device__ __half g_w2t[DIMC * HID];            // (diag(s) w2)^T [n][k]
__device__ float  g_b2p[DIMC];                  // grn_b @ w2 + b2

// ======================= helpers ===========================================
__device__ __forceinline__ uint32_t smem_u32(const void* p) {
    uint32_t a;
    asm("{ .reg .u64 t; cvta.to.shared.u64 t, %1; cvt.u32.u64 %0, t; }" : "=r"(a) : "l"(p));
    return a;
}
__device__ __forceinline__ float gelu_exact(float v) {
    return 0.5f * v * (1.0f + erff(v * 0.70710678118654752f));
}
// swizzled byte offset within a [rows][64 fp16] (128B/row) smem tile
__device__ __forceinline__ uint32_t sw_off(int row, int u) {   // u = 16B unit 0..7
    return (uint32_t)((row * 128 + u * 16) ^ ((row & 7) << 4));
}
__device__ __forceinline__ void ldsm4(uint32_t* r, uint32_t addr) {
    asm volatile("ldmatrix.sync.aligned.m8n8.x4.shared.b16 {%0,%1,%2,%3}, [%4];"
        : "=r"(r[0]), "=r"(r[1]), "=r"(r[2]), "=r"(r[3]) : "r"(addr));
}
__device__ __forceinline__ void mma16816(float* c, const uint32_t* a, const uint32_t* b) {
    asm volatile("mma.sync.aligned.m16n8k16.row.col.f32.f16.f16.f32 "
        "{%0,%1,%2,%3}, {%4,%5,%6,%7}, {%8,%9}, {%0,%1,%2,%3};"
        : "+f"(c[0]), "+f"(c[1]), "+f"(c[2]), "+f"(c[3])
        : "r"(a[0]), "r"(a[1]), "r"(a[2]), "r"(a[3]), "r"(b[0]), "r"(b[1]));
}
__device__ __forceinline__ void cp16(uint32_t dst, const void* src, bool pred) {
    int sz = pred ? 16 : 0;
    asm volatile("cp.async.cg.shared.global [%0], [%1], 16, %2;"
        :: "r"(dst), "l"(src), "r"(sz));
}
#define CP_COMMIT() asm volatile("cp.async.commit_group;" ::: "memory")
#define CP_WAIT(N)  asm volatile("cp.async.wait_group %0;" :: "n"(N) : "memory")

// ---------------- Kernel A: sparse depthwise conv + LayerNorm -> fp16 ------
// One warp per site. All 11 nbr chunk-values prefetched into registers:
// 11 independent LDGs in flight (one latency) instead of a serial chain.
#define NCHUNK 11   // ceil(343/32)
__global__ __launch_bounds__(256) void dwconv_ln_k(
    const float* __restrict__ feats, const int* __restrict__ nbr,
    const float* __restrict__ dw_w, const float* __restrict__ dw_b,
    const float* __restrict__ ln_g, const float* __restrict__ ln_b, int n)
{
    int site = (blockIdx.x * blockDim.x + threadIdx.x) >> 5;
    int lane = threadIdx.x & 31;
    if (site >= n) return;

    const int* row = nbr + (size_t)site * KTAPS;

    int idxs[NCHUNK];
    #pragma unroll
    for (int c = 0; c < NCHUNK; c++) {
        int k = c * 32 + lane;
        idxs[c] = (k < KTAPS) ? __ldg(row + k) : n;
    }

    float4 acc = make_float4(0.f, 0.f, 0.f, 0.f);

    #pragma unroll
    for (int c = 0; c < NCHUNK; c++) {
        unsigned valid = __ballot_sync(0xffffffffu, idxs[c] < n);
        while (valid) {
            int b = __ffs(valid) - 1;
            valid &= valid - 1;
            int j  = __shfl_sync(0xffffffffu, idxs[c], b);
            int kk = c * 32 + b;
            float4 f = *(const float4*)(feats + (size_t)j * DIMC + lane * 4);
            float4 w = *(const float4*)(dw_w + kk * DIMC + lane * 4);
            acc.x = fmaf(f.x, w.x, acc.x);
            acc.y = fmaf(f.y, w.y, acc.y);
            acc.z = fmaf(f.z, w.z, acc.z);
            acc.w = fmaf(f.w, w.w, acc.w);
        }
    }
    float4 bb = *(const float4*)(dw_b + lane * 4);
    acc.x += bb.x; acc.y += bb.y; acc.z += bb.z; acc.w += bb.w;

    float s1 = acc.x + acc.y + acc.z + acc.w;
    float s2 = acc.x*acc.x + acc.y*acc.y + acc.z*acc.z + acc.w*acc.w;
    #pragma unroll
    for (int o = 16; o; o >>= 1) {
        s1 += __shfl_xor_sync(0xffffffffu, s1, o);
        s2 += __shfl_xor_sync(0xffffffffu, s2, o);
    }
    float mean = s1 * (1.f / DIMC);
    float var  = s2 * (1.f / DIMC) - mean * mean;
    float rstd = rsqrtf(var + 1e-6f);

    float4 g = *(const float4*)(ln_g + lane * 4);
    float4 b = *(const float4*)(ln_b + lane * 4);
    float v0 = (acc.x - mean) * rstd * g.x + b.x;
    float v1 = (acc.y - mean) * rstd * g.y + b.y;
    float v2 = (acc.z - mean) * rstd * g.z + b.z;
    float v3 = (acc.w - mean) * rstd * g.w + b.w;

    size_t o = (size_t)site * DIMC + lane * 4;
    *(half2*)(g_x1 + o)     = __floats2half2_rn(v0, v1);
    *(half2*)(g_x1 + o + 2) = __floats2half2_rn(v2, v3);
}

// ---------------- prep: w1t[n][k] = fp16(w1[k][n]); also zero ssq ----------
__global__ void w1t_prep_k(const float* __restrict__ w1)
{
    int idx = blockIdx.x * blockDim.x + threadIdx.x;   // 65536 = 512*128
    if (idx < HID) g_ssq[idx] = 0.f;
    if (idx < HID * DIMC) {
        int nrow = idx >> 7, k = idx & 127;
        g_w1t[idx] = __float2half_rn(w1[(size_t)k * HID + nrow]);
    }
}

// ============== async chunk loader =========================================
__device__ __forceinline__ void load_chunk_async(
    uint32_t sA, uint32_t sB,
    const __half* __restrict__ A, int a_stride,
    const __half* __restrict__ B, int b_stride,
    int m0, int n_valid, int nb0, int kc, int tid)
{
    #pragma unroll
    for (int i = 0; i < 2; i++) {
        int idx = tid + i * 512;
        int row = idx >> 3, u = idx & 7;
        bool ok = (m0 + row < n_valid);
        size_t go = (size_t)(m0 + row) * a_stride + kc * 64 + u * 8;
        cp16(sA + sw_off(row, u), A + go, ok);
    }
    #pragma unroll
    for (int i = 0; i < 2; i++) {
        int idx = tid + i * 512;
        int row = idx >> 3, u = idx & 7;
        size_t go = (size_t)(nb0 + row) * b_stride + kc * 64 + u * 8;
        cp16(sB + sw_off(row, u), B + go, true);
    }
    CP_COMMIT();
}

// ---------------- Kernel B: GEMM1  h = gelu(x1 @ w1 + b1), + ssq -----------
// Block 128M x 128N, K=128 (2 chunks of 64), 512 thr = 16 warps (4m x 4n),
// warp tile 32x32. smem: 2 stages x (A 16KB + B 16KB) = 64KB. 2 CTAs/SM.
// (exact config from the 350.3us-verified run)
__global__ __launch_bounds__(512, 2) void gemm1_tc(const float* __restrict__ b1, int n)
{
    extern __shared__ char smem[];
    const int STG = 32768;
    __shared__ float scs[128];

    int tid = threadIdx.x;
    int wid = tid >> 5, lane = tid & 31;
    int wm = wid >> 2, wn = wid & 3;
    int lr = lane & 15, lh = lane >> 4;
    int m0 = blockIdx.x * 128;
    int n0 = blockIdx.y * 128;

    if (tid < 128) scs[tid] = 0.f;

    uint32_t base = smem_u32(smem);
    uint32_t arow0 = (uint32_t)((wm * 32 + lr) * 128);
    uint32_t brow0 = (uint32_t)((wn * 32 + lr) * 128);
    uint32_t sx    = (uint32_t)((lr & 7) << 4);

    float acc[2][4][4];
    #pragma unroll
    for (int mf = 0; mf < 2; mf++)
        #pragma unroll
        for (int nf = 0; nf < 4; nf++)
            #pragma unroll
            for (int r = 0; r < 4; r++) acc[mf][nf][r] = 0.f;

    #pragma unroll
    for (int kc = 0; kc < 2; kc++) {
        uint32_t sb = base + kc * STG;
        load_chunk_async(sb, sb + 16384,
                         g_x1, DIMC, g_w1t, DIMC,
                         m0, n, n0, kc, tid);
    }

    #pragma unroll
    for (int kc = 0; kc < 2; kc++) {
        if (kc == 0) { CP_WAIT(1); } else { CP_WAIT(0); }
        __syncthreads();
        uint32_t uA = base + kc * STG, uB = uA + 16384;
        #pragma unroll
        for (int ks = 0; ks < 4; ks++) {
            uint32_t xu = (uint32_t)(((ks * 2 + lh) << 4)) ^ sx;
            uint32_t ah[2][4];
            #pragma unroll
            for (int mf = 0; mf < 2; mf++)
                ldsm4(ah[mf], uA + arow0 + mf * 2048 + xu);
            #pragma unroll
            for (int nh = 0; nh < 2; nh++) {
                uint32_t t[4], bf[2][2];
                ldsm4(t, uB + brow0 + nh * 2048 + xu);
                bf[0][0] = t[0]; bf[0][1] = t[2];
                bf[1][0] = t[1]; bf[1][1] = t[3];
                #pragma unroll
                for (int mf = 0; mf < 2; mf++)
                    #pragma unroll
                    for (int j = 0; j < 2; j++)
                        mma16816(acc[mf][nh * 2 + j], ah[mf], bf[j]);
            }
        }
        __syncthreads();
    }

    // epilogue: bias + GELU, fp16 store, per-column ssq (fp32, unrounded)
    int g = lane >> 2, q = lane & 3;
    float csq[8];
    #pragma unroll
    for (int i = 0; i < 8; i++) csq[i] = 0.f;
    #pragma unroll
    for (int mf = 0; mf < 2; mf++) {
        #pragma unroll
        for (int nf = 0; nf < 4; nf++) {
            int col = n0 + wn * 32 + nf * 8 + q * 2;
            float bia0 = b1[col], bia1 = b1[col + 1];
            #pragma unroll
            for (int half_i = 0; half_i < 2; half_i++) {
                int m = m0 + wm * 32 + mf * 16 + g + half_i * 8;
                if (m < n) {
                    float v0 = gelu_exact(acc[mf][nf][half_i*2+0] + bia0);
                    float v1 = gelu_exact(acc[mf][nf][half_i*2+1] + bia1);
                    *(half2*)(g_h + (size_t)m * HID + col) = __floats2half2_rn(v0, v1);
                    csq[nf*2+0] += v0 * v0;
                    csq[nf*2+1] += v1 * v1;
                }
            }
        }
    }
    __syncthreads();
    #pragma unroll
    for (int nf = 0; nf < 4; nf++) {
        atomicAdd(&scs[wn * 32 + nf * 8 + q * 2],     csq[nf*2+0]);
        atomicAdd(&scs[wn * 32 + nf * 8 + q * 2 + 1], csq[nf*2+1]);
    }
    __syncthreads();
    if (tid < 128) atomicAdd(&g_ssq[n0 + tid], scs[tid]);
}

// ---------------- Kernel D1: GRN channel scale -----------------------------
__global__ void grn_scale_k(const float* __restrict__ grn_g)
{
    int c = threadIdx.x;            // 512 threads, 1 block
    float gx = sqrtf(g_ssq[c]);
    __shared__ float red[16];
    __shared__ float mean_s;
    float v = gx;
    #pragma unroll
    for (int o = 16; o; o >>= 1) v += __shfl_xor_sync(0xffffffffu, v, o);
    if ((c & 31) == 0) red[c >> 5] = v;
    __syncthreads();
    if (c < 16) {
        float w = red[c];
        #pragma unroll
        for (int o = 8; o; o >>= 1) w += __shfl_xor_sync(0xffffu, w, o);
        if (c == 0) mean_s = w * (1.f / HID);
    }
    __syncthreads();
    float nx = gx / (mean_s + 1e-6f);
    g_s[c] = grn_g[c] * nx + 1.0f;
}

// ---------------- Kernel D2: w2t[n][k] = fp16(s[k]*w2[k][n]) ---------------
__global__ void build_w2t_k(const float* __restrict__ w2)
{
    int idx = blockIdx.x * blockDim.x + threadIdx.x;   // 65536 = 128*512
    if (idx < DIMC * HID) {
        int nrow = idx >> 9, k = idx & 511;
        g_w2t[idx] = __float2half_rn(g_s[k] * w2[(size_t)k * DIMC + nrow]);
    }
}

// ---------------- Kernel D3: b2' = grn_b @ w2 + b2 -------------------------
__global__ void build_b2p_k(const float* __restrict__ grn_b,
                            const float* __restrict__ w2,
                            const float* __restrict__ b2)
{
    int c = threadIdx.x;            // 128 threads
    float acc = 0.f;
    for (int k = 0; k < HID; k++) acc = fmaf(grn_b[k], w2[(size_t)k * DIMC + c], acc);
    g_b2p[c] = b2[c] + acc;
}

// ---------------- Kernel E: GEMM2  out = h @ w2' + b2' + feats -------------
// Block 128M x 128N, K=512 (8 chunks, 3-stage cp.async ring: 2 chunks in
// flight), 512 thr, warp 32x32. smem: 3 x 32KB = 96KB. 2 CTAs/SM.
__global__ __launch_bounds__(512, 2) void gemm2_tc(
    const float* __restrict__ feats, float* __restrict__ out, int n)
{
    extern __shared__ char smem[];
    const int STG = 32768;

    int tid = threadIdx.x;
    int wid = tid >> 5, lane = tid & 31;
    int wm = wid >> 2, wn = wid & 3;
    int lr = lane & 15, lh = lane >> 4;
    int m0 = blockIdx.x * 128;

    uint32_t base = smem_u32(smem);
    uint32_t arow0 = (uint32_t)((wm * 32 + lr) * 128);
    uint32_t brow0 = (uint32_t)((wn * 32 + lr) * 128);
    uint32_t sx    = (uint32_t)((lr & 7) << 4);

    float acc[2][4][4];
    #pragma unroll
    for (int mf = 0; mf < 2; mf++)
        #pragma unroll
        for (int nf = 0; nf < 4; nf++)
            #pragma unroll
            for (int r = 0; r < 4; r++) acc[mf][nf][r] = 0.f;

    // prologue: chunks 0 and 1 in flight
    #pragma unroll
    for (int kc = 0; kc < 2; kc++) {
        uint32_t sb = base + kc * STG;
        load_chunk_async(sb, sb + 16384, g_h, HID, g_w2t, HID,
                         m0, n, 0, kc, tid);
    }

    for (int kc = 0; kc < 8; kc++) {
        if (kc < 6) {
            int st = (kc + 2) % 3;
            uint32_t sb = base + st * STG;
            load_chunk_async(sb, sb + 16384, g_h, HID, g_w2t, HID,
                             m0, n, 0, kc + 2, tid);
            CP_WAIT(2);                 // chunk kc complete; kc+1,kc+2 pending
        } else if (kc == 6) {
            CP_WAIT(1);                 // chunk 6 complete; 7 pending
        } else {
            CP_WAIT(0);
        }
        __syncthreads();

        uint32_t uA = base + (kc % 3) * STG, uB = uA + 16384;
        #pragma unroll
        for (int ks = 0; ks < 4; ks++) {
            uint32_t xu = (uint32_t)(((ks * 2 + lh) << 4)) ^ sx;
            uint32_t ah[2][4];
            #pragma unroll
            for (int mf = 0; mf < 2; mf++)
                ldsm4(ah[mf], uA + arow0 + mf * 2048 + xu);
            #pragma unroll
            for (int nh = 0; nh < 2; nh++) {
                uint32_t t[4], bf[2][2];
                ldsm4(t, uB + brow0 + nh * 2048 + xu);
                bf[0][0] = t[0]; bf[0][1] = t[2];
                bf[1][0] = t[1]; bf[1][1] = t[3];
                #pragma unroll
                for (int mf = 0; mf < 2; mf++)
                    #pragma unroll
                    for (int j = 0; j < 2; j++)
                        mma16816(acc[mf][nh * 2 + j], ah[mf], bf[j]);
            }
        }
        __syncthreads();
    }

    // epilogue: + b2' + feats residual, fp32 out
    int g = lane >> 2, q = lane & 3;
    #pragma unroll
    for (int mf = 0; mf < 2; mf++) {
        #pragma unroll
        for (int nf = 0; nf < 4; nf++) {
            int col = wn * 32 + nf * 8 + q * 2;
            float b0 = g_b2p[col], b1v = g_b2p[col + 1];
            #pragma unroll
            for (int half_i = 0; half_i < 2; half_i++) {
                int m = m0 + wm * 32 + mf * 16 + g + half_i * 8;
                if (m < n) {
                    size_t o = (size_t)m * DIMC + col;
                    float2 fr = *(const float2*)(feats + o);
                    float2 ov;
                    ov.x = acc[mf][nf][half_i*2+0] + b0  + fr.x;
                    ov.y = acc[mf][nf][half_i*2+1] + b1v + fr.y;
                    *(float2*)(out + o) = ov;
                }
            }
        }
    }
}

// ---------------------------------------------------------------------------
extern "C" void kernel_launch(void* const* d_in, const int* in_sizes, int n_in,
                              void* d_out, int out_size)
{
    const float* feats = (const float*)d_in[0];
    const int*   nbr   = (const int*)  d_in[1];
    const float* dw_w  = (const float*)d_in[2];
    const float* dw_b  = (const float*)d_in[3];
    const float* ln_g  = (const float*)d_in[4];
    const float* ln_b  = (const float*)d_in[5];
    const float* w1    = (const float*)d_in[6];
    const float* b1    = (const float*)d_in[7];
    const float* grn_g = (const float*)d_in[8];
    const float* grn_b = (const float*)d_in[9];
    const float* w2    = (const float*)d_in[10];
    const float* b2    = (const float*)d_in[11];
    float* out = (float*)d_out;

    int n = in_sizes[0] / DIMC;

    const int SMEM1 = 64 * 1024;
    const int SMEM2 = 96 * 1024;
    cudaFuncSetAttribute(gemm1_tc, cudaFuncAttributeMaxDynamicSharedMemorySize, SMEM1);
    cudaFuncSetAttribute(gemm2_tc, cudaFuncAttributeMaxDynamicSharedMemorySize, SMEM2);

    int blocks_a = (n * 32 + 255) / 256;
    dwconv_ln_k<<<blocks_a, 256>>>(feats, nbr, dw_w, dw_b, ln_g, ln_b, n);

    w1t_prep_k<<<(HID * DIMC + 255) / 256, 256>>>(w1);

    int mtiles = (n + 127) / 128;
    dim3 g1(mtiles, 4);                        // R8-verified grid order
    gemm1_tc<<<g1, 512, SMEM1>>>(b1, n);

    grn_scale_k<<<1, HID>>>(grn_g);
    build_w2t_k<<<(DIMC * HID + 255) / 256, 256>>>(w2);
    build_b2p_k<<<1, DIMC>>>(grn_b, w2, b2);

    gemm2_tc<<<mtiles, 512, SMEM2>>>(feats, out, n);
}